// round 8
// baseline (speedup 1.0000x reference)
#include <cuda_runtime.h>
#include <cuda_bf16.h>
#include <cstdint>

// Problem constants
#define B_ 2
#define H_ 8
#define N_ 512
#define D_ 16
#define E_ 128
#define HD 128
#define TM 64               // m-rows per tile
#define NTILES 8
#define THREADS 512

// smem layout (bytes). A/W rows are 128 bf16 = 256 B.
#define SM_Q     0                      // 512 B   q row, head-major
#define SM_S     512                    // 16384 B scores [H][N]
#define SM_RED   16896                  // 64 B    softmax partials [H][2]
#define SM_OBUF  16960                  // 512 B   output partials [H][16]
#define SM_A     17920                  // 2 x 32768 B : {z_hi[64][128], z_lo[64][128]} x 2 bufs
#define SM_ABUF  32768
#define SM_ALO   16384                  // lo offset within a buffer
#define SM_WH    (SM_A + 2 * SM_ABUF)   // 65536 B W_hi [256n][128k] (cols interleaved Wz1/Wz2)
#define SM_WL    (SM_WH + 65536)        // 65536 B W_lo
#define SM_TOTAL (SM_WL + 65536)        // 214528 B

__device__ __forceinline__ uint32_t smem_u32(const void* p) {
    uint32_t r;
    asm("{ .reg .u64 t; cvta.to.shared.u64 t, %1; cvt.u32.u64 %0, t; }" : "=r"(r) : "l"(p));
    return r;
}
__device__ __forceinline__ void ldsm_x4(uint32_t (&r)[4], uint32_t addr) {
    asm volatile("ldmatrix.sync.aligned.m8n8.x4.shared.b16 {%0,%1,%2,%3}, [%4];"
                 : "=r"(r[0]), "=r"(r[1]), "=r"(r[2]), "=r"(r[3]) : "r"(addr));
}
#define MMA_BF16(d, a, b0v, b1v) \
    asm volatile("mma.sync.aligned.m16n8k16.row.col.f32.bf16.bf16.f32 " \
        "{%0,%1,%2,%3}, {%4,%5,%6,%7}, {%8,%9}, {%0,%1,%2,%3};" \
        : "+f"((d)[0]), "+f"((d)[1]), "+f"((d)[2]), "+f"((d)[3]) \
        : "r"((a)[0]), "r"((a)[1]), "r"((a)[2]), "r"((a)[3]), "r"(b0v), "r"(b1v))

__device__ __forceinline__ uint32_t pack_bf2(float a, float b) {
    __nv_bfloat162 p = __float22bfloat162_rn(make_float2(a, b));  // .x=a (low half)
    return *reinterpret_cast<uint32_t*>(&p);
}
__device__ __forceinline__ float bf_lo(uint32_t w) { return __uint_as_float(w << 16); }
__device__ __forceinline__ float bf_hi(uint32_t w) { return __uint_as_float(w & 0xFFFF0000u); }

__global__ void __launch_bounds__(THREADS, 1)
mixed_attn_ws(const float* __restrict__ q, const float* __restrict__ k,
              const float* __restrict__ v, const float* __restrict__ z,
              const float* __restrict__ Wz1, const float* __restrict__ Wz2,
              float* __restrict__ out)
{
    extern __shared__ char smem[];
    const uint32_t smem_base = smem_u32(smem);
    float* q_sm   = (float*)(smem + SM_Q);
    float* s_sm   = (float*)(smem + SM_S);
    float* red_sm = (float*)(smem + SM_RED);
    float* obuf   = (float*)(smem + SM_OBUF);

    const int tid  = threadIdx.x;
    const int wid  = tid >> 5;
    const int lane = tid & 31;
    const int g    = lane >> 2;
    const int tig  = lane & 3;
    const int n = blockIdx.x, b = blockIdx.y;

    // =========================== PROLOGUE ===========================
    if (wid < 8) {
        // ---- consumers: q + W -> bf16 hi/lo (interleaved cols: even=Wz1, odd=Wz2)
        if (tid < HD) {
            int h = tid >> 4, d = tid & 15;
            q_sm[tid] = q[(((size_t)b * H_ + h) * N_ + n) * D_ + d];
        }
        const int nn = tid;               // 0..255, one W row per thread
        const float* Wsrc = (nn & 1) ? Wz2 : Wz1;
        const int c = nn >> 1;
        char* WH = smem + SM_WH + nn * 256;
        char* WL = smem + SM_WL + nn * 256;
        const int xr = (nn & 7);
        #pragma unroll 4
        for (int e = 0; e < E_; e += 2) {
            float w0 = Wsrc[e * HD + c];
            float w1 = Wsrc[(e + 1) * HD + c];
            uint32_t hi = pack_bf2(w0, w1);
            uint32_t lo = pack_bf2(w0 - bf_lo(hi), w1 - bf_hi(hi));
            int sw = ((((e >> 3) ^ xr) << 4)) + (e & 7) * 2;
            *(uint32_t*)(WH + sw) = hi;
            *(uint32_t*)(WL + sw) = lo;
        }
    }

    // producer thread mapping (rows of the 64-row tile)
    const int mrow = ((wid - 8) << 3) + (lane >> 2);   // 0..63 for producers
    const int e0   = (lane & 3) * 32;
    const float* zrow = z + (((size_t)b * N_ + n) * N_ + mrow) * E_ + e0;
    float4 zreg[8];

    if (wid >= 8) {
        // ---- producers: z tile 0 -> convert -> A buf 0 ; then prefetch z tile 1
        #pragma unroll
        for (int j = 0; j < 8; j++) zreg[j] = ((const float4*)zrow)[j];
        {
            char* AH = smem + SM_A + mrow * 256;
            char* AL = smem + SM_A + SM_ALO + mrow * 256;
            const int xr = mrow & 7;
            #pragma unroll
            for (int j = 0; j < 8; j++) {
                const int e = e0 + j * 4;
                float4 f = zreg[j];
                uint32_t h01 = pack_bf2(f.x, f.y);
                uint32_t h23 = pack_bf2(f.z, f.w);
                uint32_t l01 = pack_bf2(f.x - bf_lo(h01), f.y - bf_hi(h01));
                uint32_t l23 = pack_bf2(f.z - bf_lo(h23), f.w - bf_hi(h23));
                int sw = (((e >> 3) ^ xr) << 4) + (e & 4) * 2;
                *(uint2*)(AH + sw) = make_uint2(h01, h23);
                *(uint2*)(AL + sw) = make_uint2(l01, l23);
            }
        }
        #pragma unroll
        for (int j = 0; j < 8; j++) zreg[j] = ((const float4*)(zrow + (size_t)TM * E_))[j];
    }
    __syncthreads();   // W, q, A0 ready

    // consumer warp tiling: 8 warps = 2 m-blocks (32 rows) x 4 n-blocks (64 cols = 2 heads)
    const int mblk  = (wid & 1) * 32;
    const int nq    = wid >> 1;            // 0..3 for consumers
    const int nbase = nq * 64;

    const int laneX = lane & 7;
    const uint32_t arow_off = (uint32_t)(mblk + ((lane >> 3) & 1) * 8 + laneX) * 256;
    const int asel = lane >> 4;
    const uint32_t brow = smem_base + (uint32_t)(nbase + ((lane >> 4) & 1) * 8 + laneX) * 256;
    const int bsel = (lane >> 3) & 1;

    // ========================== MAIN WINDOWS ==========================
    for (int t = 0; t < NTILES; t++) {
        if (wid < 8) {
            // ---------------- consumers: MMA tile t from A[t&1] ----------------
            const uint32_t abase = smem_base + SM_A + (uint32_t)(t & 1) * SM_ABUF + arow_off;

            float acc[2][8][4];
            #pragma unroll
            for (int mt = 0; mt < 2; mt++)
                #pragma unroll
                for (int nt = 0; nt < 8; nt++)
                    #pragma unroll
                    for (int i = 0; i < 4; i++) acc[mt][nt][i] = 0.f;

            #pragma unroll 1
            for (int ks = 0; ks < 8; ks++) {
                // -- load ALL fragments for this k-chunk up front (12 LDSM.x4)
                uint32_t ah[2][4], al[2][4], bh[4][4], bl[4][4];
                const uint32_t aoff = abase + ((uint32_t)((ks * 2 + asel) ^ laneX) << 4);
                ldsm_x4(ah[0], aoff);
                ldsm_x4(ah[1], aoff + 16 * 256);
                ldsm_x4(al[0], aoff + SM_ALO);
                ldsm_x4(al[1], aoff + SM_ALO + 16 * 256);
                const uint32_t boff = ((uint32_t)((ks * 2 + bsel) ^ laneX) << 4);
                #pragma unroll
                for (int ntp = 0; ntp < 4; ntp++) {
                    const uint32_t ba = brow + (uint32_t)ntp * (16 * 256) + boff;
                    ldsm_x4(bh[ntp], ba + SM_WH);
                    ldsm_x4(bl[ntp], ba + SM_WL);
                }
                // -- split-major passes: each acc touched once per pass
                //    (RAW distance = 16 HMMA >> HMMA latency)
                #pragma unroll
                for (int ntp = 0; ntp < 4; ntp++)      // pass 0: hi x hi
                    #pragma unroll
                    for (int mt = 0; mt < 2; mt++) {
                        MMA_BF16(acc[mt][2 * ntp],     ah[mt], bh[ntp][0], bh[ntp][1]);
                        MMA_BF16(acc[mt][2 * ntp + 1], ah[mt], bh[ntp][2], bh[ntp][3]);
                    }
                #pragma unroll
                for (int ntp = 0; ntp < 4; ntp++)      // pass 1: lo x hi
                    #pragma unroll
                    for (int mt = 0; mt < 2; mt++) {
                        MMA_BF16(acc[mt][2 * ntp],     al[mt], bh[ntp][0], bh[ntp][1]);
                        MMA_BF16(acc[mt][2 * ntp + 1], al[mt], bh[ntp][2], bh[ntp][3]);
                    }
                #pragma unroll
                for (int ntp = 0; ntp < 4; ntp++)      // pass 2: hi x lo
                    #pragma unroll
                    for (int mt = 0; mt < 2; mt++) {
                        MMA_BF16(acc[mt][2 * ntp],     ah[mt], bl[ntp][0], bl[ntp][1]);
                        MMA_BF16(acc[mt][2 * ntp + 1], ah[mt], bl[ntp][2], bl[ntp][3]);
                    }
            }

            // ---- scores from fragments: col pair (2j,2j+1) = (p1[d], p2[d])
            #pragma unroll
            for (int hh = 0; hh < 2; hh++) {
                const int h = nq * 2 + hh;
                const float* kh = k + (((size_t)b * H_ + h) * N_) * D_;
                const float* qh = q_sm + h * 16;
                float sa[2][2] = {{0.f, 0.f}, {0.f, 0.f}};
                #pragma unroll
                for (int ntl = 0; ntl < 4; ntl++) {
                    const int nt = hh * 4 + ntl;
                    const int d = ntl * 4 + tig;
                    const float qv = qh[d];
                    #pragma unroll
                    for (int mt = 0; mt < 2; mt++) {
                        const int mg = t * TM + mblk + mt * 16 + g;
                        float kv0 = kh[(size_t)mg * 16 + d];
                        float kv1 = kh[(size_t)(mg + 8) * 16 + d];
                        sa[mt][0] += (qv + acc[mt][nt][0]) * (kv0 + acc[mt][nt][1]);
                        sa[mt][1] += (qv + acc[mt][nt][2]) * (kv1 + acc[mt][nt][3]);
                    }
                }
                #pragma unroll
                for (int mt = 0; mt < 2; mt++)
                    #pragma unroll
                    for (int r = 0; r < 2; r++) {
                        float s = sa[mt][r];
                        s += __shfl_xor_sync(0xffffffffu, s, 1);
                        s += __shfl_xor_sync(0xffffffffu, s, 2);
                        if (tig == 0) {
                            const int mg = t * TM + mblk + mt * 16 + g + r * 8;
                            s_sm[h * N_ + mg] = s * 0.25f;   // 1/sqrt(D), D=16
                        }
                    }
            }
        } else {
            // ---------------- producers: convert tile t+1 into A[(t+1)&1] ----------------
            if (t + 1 < NTILES) {
                char* AH = smem + SM_A + ((t + 1) & 1) * SM_ABUF + mrow * 256;
                char* AL = AH + SM_ALO;
                const int xr = mrow & 7;
                #pragma unroll
                for (int j = 0; j < 8; j++) {
                    const int e = e0 + j * 4;
                    float4 f = zreg[j];
                    uint32_t h01 = pack_bf2(f.x, f.y);
                    uint32_t h23 = pack_bf2(f.z, f.w);
                    uint32_t l01 = pack_bf2(f.x - bf_lo(h01), f.y - bf_hi(h01));
                    uint32_t l23 = pack_bf2(f.z - bf_lo(h23), f.w - bf_hi(h23));
                    int sw = (((e >> 3) ^ xr) << 4) + (e & 4) * 2;
                    *(uint2*)(AH + sw) = make_uint2(h01, h23);
                    *(uint2*)(AL + sw) = make_uint2(l01, l23);
                }
            }
            if (t + 2 < NTILES) {
                const float4* zp = (const float4*)(zrow + (size_t)(t + 2) * TM * E_);
                #pragma unroll
                for (int j = 0; j < 8; j++) zreg[j] = zp[j];
            }
        }
        __syncthreads();
    }

    // ---- softmax + output: 2 warps per head (wid&7 = head, wid>>3 = m-half)
    {
        const int h    = wid & 7;
        const int half = wid >> 3;
        float* srow = s_sm + h * N_;

        float mx = -1e30f;
        for (int m = lane; m < N_; m += 32) mx = fmaxf(mx, srow[m]);
        #pragma unroll
        for (int o = 16; o > 0; o >>= 1) mx = fmaxf(mx, __shfl_xor_sync(0xffffffffu, mx, o));

        float psum = 0.f;
        const int mbeg = half * (N_ / 2);
        for (int m = mbeg + lane; m < mbeg + N_ / 2; m += 32) {
            float e = __expf(srow[m] - mx);
            srow[m] = e;
            psum += e;
        }
        #pragma unroll
        for (int o = 16; o > 0; o >>= 1) psum += __shfl_xor_sync(0xffffffffu, psum, o);
        if (lane == 0) red_sm[h * 2 + half] = psum;
        __syncthreads();
        const float sum = red_sm[h * 2] + red_sm[h * 2 + 1];

        const int d   = lane & 15;
        const int sub = lane >> 4;
        const float* vp = v + (((size_t)b * H_ + h) * N_) * D_;
        float oacc = 0.f;
        const int m0 = mbeg + sub * (N_ / 4);
        #pragma unroll 4
        for (int m = m0; m < m0 + N_ / 4; m++)
            oacc += srow[m] * vp[(size_t)m * D_ + d];
        oacc += __shfl_xor_sync(0xffffffffu, oacc, 16);
        if (half == 1 && sub == 0) obuf[h * 16 + d] = oacc;
        __syncthreads();
        if (half == 0 && sub == 0)
            out[((size_t)b * N_ + n) * HD + h * 16 + d] = (oacc + obuf[h * 16 + d]) / sum;
    }
}

extern "C" void kernel_launch(void* const* d_in, const int* in_sizes, int n_in,
                              void* d_out, int out_size) {
    const float* q   = (const float*)d_in[0];
    const float* k   = (const float*)d_in[1];
    const float* v   = (const float*)d_in[2];
    const float* z   = (const float*)d_in[3];
    const float* Wz1 = (const float*)d_in[4];
    const float* Wz2 = (const float*)d_in[5];
    float* out = (float*)d_out;

    cudaFuncSetAttribute(mixed_attn_ws,
                         cudaFuncAttributeMaxDynamicSharedMemorySize, SM_TOTAL);
    dim3 grid(N_, B_);
    mixed_attn_ws<<<grid, THREADS, SM_TOTAL>>>(q, k, v, z, Wz1, Wz2, out);
}

// round 9
// speedup vs baseline: 1.0601x; 1.0601x over previous
#include <cuda_runtime.h>
#include <cuda_bf16.h>
#include <cstdint>

// Problem constants
#define B_ 2
#define H_ 8
#define N_ 512
#define D_ 16
#define E_ 128
#define HD 128
#define TM 64               // m-rows per tile
#define NTILES 8
#define THREADS 512

// smem layout (bytes). A/W rows are 128 bf16 = 256 B.
#define SM_Q     0                      // 512 B   q row, head-major
#define SM_S     512                    // 16384 B scores [H][N]
#define SM_RED   16896                  // 64 B    softmax partials [H][2]
#define SM_OBUF  16960                  // 512 B   output partials [H][16]
#define SM_A     17920                  // 2 x 32768 B : {z_hi[64][128], z_lo[64][128]} x 2 bufs
#define SM_ABUF  32768
#define SM_ALO   16384                  // lo offset within a buffer
#define SM_WH    (SM_A + 2 * SM_ABUF)   // 65536 B W_hi [256n][128k] (d-permuted, interleaved Wz1/Wz2)
#define SM_WL    (SM_WH + 65536)        // 65536 B W_lo
#define SM_TOTAL (SM_WL + 65536)        // 214528 B

__device__ __forceinline__ uint32_t smem_u32(const void* p) {
    uint32_t r;
    asm("{ .reg .u64 t; cvta.to.shared.u64 t, %1; cvt.u32.u64 %0, t; }" : "=r"(r) : "l"(p));
    return r;
}
__device__ __forceinline__ void ldsm_x4(uint32_t (&r)[4], uint32_t addr) {
    asm volatile("ldmatrix.sync.aligned.m8n8.x4.shared.b16 {%0,%1,%2,%3}, [%4];"
                 : "=r"(r[0]), "=r"(r[1]), "=r"(r[2]), "=r"(r[3]) : "r"(addr));
}
#define MMA_BF16(d, a, b0v, b1v) \
    asm volatile("mma.sync.aligned.m16n8k16.row.col.f32.bf16.bf16.f32 " \
        "{%0,%1,%2,%3}, {%4,%5,%6,%7}, {%8,%9}, {%0,%1,%2,%3};" \
        : "+f"((d)[0]), "+f"((d)[1]), "+f"((d)[2]), "+f"((d)[3]) \
        : "r"((a)[0]), "r"((a)[1]), "r"((a)[2]), "r"((a)[3]), "r"(b0v), "r"(b1v))

__device__ __forceinline__ uint32_t pack_bf2(float a, float b) {
    __nv_bfloat162 p = __float22bfloat162_rn(make_float2(a, b));  // .x=a (low half)
    return *reinterpret_cast<uint32_t*>(&p);
}
__device__ __forceinline__ float bf_lo(uint32_t w) { return __uint_as_float(w << 16); }
__device__ __forceinline__ float bf_hi(uint32_t w) { return __uint_as_float(w & 0xFFFF0000u); }

__global__ void __launch_bounds__(THREADS, 1)
mixed_attn_ws(const float* __restrict__ q, const float* __restrict__ k,
              const float* __restrict__ v, const float* __restrict__ z,
              const float* __restrict__ Wz1, const float* __restrict__ Wz2,
              float* __restrict__ out)
{
    extern __shared__ char smem[];
    const uint32_t smem_base = smem_u32(smem);
    float* q_sm   = (float*)(smem + SM_Q);
    float* s_sm   = (float*)(smem + SM_S);
    float* red_sm = (float*)(smem + SM_RED);
    float* obuf   = (float*)(smem + SM_OBUF);

    const int tid  = threadIdx.x;
    const int wid  = tid >> 5;
    const int lane = tid & 31;
    const int g    = lane >> 2;
    const int tig  = lane & 3;
    const int n = blockIdx.x, b = blockIdx.y;

    // =========================== PROLOGUE ===========================
    if (wid < 8) {
        // ---- consumers: q + W -> bf16 hi/lo.
        // d-PERMUTED column placement: smem n-row nn encodes
        //   h = nn>>5, ntl = (nn>>3)&3, tig = (nn>>1)&3, src = nn&1
        // and holds source column  c = h*16 + 4*tig + ntl  of (src? Wz2 : Wz1).
        // => fragment position (ntl, tig) sees d = 4*tig + ntl (contiguous per thread).
        if (tid < HD) {
            int h = tid >> 4, d = tid & 15;
            q_sm[tid] = q[(((size_t)b * H_ + h) * N_ + n) * D_ + d];
        }
        const int nn = tid;               // 0..255, one W row per thread
        const float* Wsrc = (nn & 1) ? Wz2 : Wz1;
        const int c = (nn >> 5) * 16 + ((nn >> 1) & 3) * 4 + ((nn >> 3) & 3);
        char* WH = smem + SM_WH + nn * 256;
        char* WL = smem + SM_WL + nn * 256;
        const int xr = (nn & 7);
        #pragma unroll 4
        for (int e = 0; e < E_; e += 2) {
            float w0 = Wsrc[e * HD + c];
            float w1 = Wsrc[(e + 1) * HD + c];
            uint32_t hi = pack_bf2(w0, w1);
            uint32_t lo = pack_bf2(w0 - bf_lo(hi), w1 - bf_hi(hi));
            int sw = ((((e >> 3) ^ xr) << 4)) + (e & 7) * 2;
            *(uint32_t*)(WH + sw) = hi;
            *(uint32_t*)(WL + sw) = lo;
        }
    }

    // producer thread mapping (rows of the 64-row tile)
    const int mrow = ((wid - 8) << 3) + (lane >> 2);   // 0..63 for producers
    const int e0   = (lane & 3) * 32;
    const float* zrow = z + (((size_t)b * N_ + n) * N_ + mrow) * E_ + e0;
    float4 zreg[8];

    if (wid >= 8) {
        // ---- producers: z tile 0 -> convert -> A buf 0 ; then prefetch z tile 1
        #pragma unroll
        for (int j = 0; j < 8; j++) zreg[j] = ((const float4*)zrow)[j];
        {
            char* AH = smem + SM_A + mrow * 256;
            char* AL = smem + SM_A + SM_ALO + mrow * 256;
            const int xr = mrow & 7;
            #pragma unroll
            for (int j = 0; j < 8; j++) {
                const int e = e0 + j * 4;
                float4 f = zreg[j];
                uint32_t h01 = pack_bf2(f.x, f.y);
                uint32_t h23 = pack_bf2(f.z, f.w);
                uint32_t l01 = pack_bf2(f.x - bf_lo(h01), f.y - bf_hi(h01));
                uint32_t l23 = pack_bf2(f.z - bf_lo(h23), f.w - bf_hi(h23));
                int sw = (((e >> 3) ^ xr) << 4) + (e & 4) * 2;
                *(uint2*)(AH + sw) = make_uint2(h01, h23);
                *(uint2*)(AL + sw) = make_uint2(l01, l23);
            }
        }
        #pragma unroll
        for (int j = 0; j < 8; j++) zreg[j] = ((const float4*)(zrow + (size_t)TM * E_))[j];
    }
    __syncthreads();   // W, q, A0 ready

    // consumer warp tiling: 8 warps = 2 m-blocks (32 rows) x 4 n-blocks (64 cols = 2 heads)
    const int mblk  = (wid & 1) * 32;
    const int nq    = wid >> 1;            // 0..3 for consumers
    const int nbase = nq * 64;

    const int laneX = lane & 7;
    const uint32_t arow_off = (uint32_t)(mblk + ((lane >> 3) & 1) * 8 + laneX) * 256;
    const int asel = lane >> 4;
    const uint32_t brow = smem_base + (uint32_t)(nbase + ((lane >> 4) & 1) * 8 + laneX) * 256;
    const int bsel = (lane >> 3) & 1;

    // ========================== MAIN WINDOWS ==========================
    for (int t = 0; t < NTILES; t++) {
        if (wid < 8) {
            // ---------------- consumers: MMA tile t from A[t&1] ----------------
            const uint32_t abase = smem_base + SM_A + (uint32_t)(t & 1) * SM_ABUF + arow_off;

            float acc[2][8][4];
            #pragma unroll
            for (int mt = 0; mt < 2; mt++)
                #pragma unroll
                for (int nt = 0; nt < 8; nt++)
                    #pragma unroll
                    for (int i = 0; i < 4; i++) acc[mt][nt][i] = 0.f;

            #pragma unroll 2
            for (int ks = 0; ks < 8; ks++) {
                uint32_t ah[2][4], al[2][4];
                const uint32_t aoff = abase + ((uint32_t)((ks * 2 + asel) ^ laneX) << 4);
                ldsm_x4(ah[0], aoff);
                ldsm_x4(ah[1], aoff + 16 * 256);
                ldsm_x4(al[0], aoff + SM_ALO);
                ldsm_x4(al[1], aoff + SM_ALO + 16 * 256);
                const uint32_t boff = ((uint32_t)((ks * 2 + bsel) ^ laneX) << 4);
                #pragma unroll
                for (int ntp = 0; ntp < 4; ntp++) {
                    uint32_t bh[4], bl[4];
                    const uint32_t ba = brow + (uint32_t)ntp * (16 * 256) + boff;
                    ldsm_x4(bh, ba + SM_WH);
                    ldsm_x4(bl, ba + SM_WL);
                    #pragma unroll
                    for (int mt = 0; mt < 2; mt++) {
                        MMA_BF16(acc[mt][2 * ntp],     ah[mt], bh[0], bh[1]);
                        MMA_BF16(acc[mt][2 * ntp + 1], ah[mt], bh[2], bh[3]);
                        MMA_BF16(acc[mt][2 * ntp],     ah[mt], bl[0], bl[1]);
                        MMA_BF16(acc[mt][2 * ntp + 1], ah[mt], bl[2], bl[3]);
                        MMA_BF16(acc[mt][2 * ntp],     al[mt], bh[0], bh[1]);
                        MMA_BF16(acc[mt][2 * ntp + 1], al[mt], bh[2], bh[3]);
                    }
                }
            }

            // ---- scores from fragments.
            // With the d-permuted W layout, fragment (ntl, tig) holds d = 4*tig + ntl,
            // so each thread's 4 d-values per row are CONTIGUOUS -> one float4 k load.
            #pragma unroll
            for (int hh = 0; hh < 2; hh++) {
                const int h = nq * 2 + hh;
                const float* kh = k + (((size_t)b * H_ + h) * N_) * D_;
                const float4 q4 = ((const float4*)(q_sm + h * 16))[tig];
                #pragma unroll
                for (int mt = 0; mt < 2; mt++) {
                    #pragma unroll
                    for (int r = 0; r < 2; r++) {
                        const int mg = t * TM + mblk + mt * 16 + r * 8 + g;
                        const float4 kv = *(const float4*)(kh + (size_t)mg * 16 + 4 * tig);
                        float s;
                        s  = (q4.x + acc[mt][hh * 4 + 0][2 * r]) * (kv.x + acc[mt][hh * 4 + 0][2 * r + 1]);
                        s += (q4.y + acc[mt][hh * 4 + 1][2 * r]) * (kv.y + acc[mt][hh * 4 + 1][2 * r + 1]);
                        s += (q4.z + acc[mt][hh * 4 + 2][2 * r]) * (kv.z + acc[mt][hh * 4 + 2][2 * r + 1]);
                        s += (q4.w + acc[mt][hh * 4 + 3][2 * r]) * (kv.w + acc[mt][hh * 4 + 3][2 * r + 1]);
                        s += __shfl_xor_sync(0xffffffffu, s, 1);
                        s += __shfl_xor_sync(0xffffffffu, s, 2);
                        if (tig == 0)
                            s_sm[h * N_ + mg] = s * 0.25f;   // 1/sqrt(D), D=16
                    }
                }
            }
        } else {
            // ---------------- producers: convert tile t+1 into A[(t+1)&1] ----------------
            if (t + 1 < NTILES) {
                char* AH = smem + SM_A + ((t + 1) & 1) * SM_ABUF + mrow * 256;
                char* AL = AH + SM_ALO;
                const int xr = mrow & 7;
                #pragma unroll
                for (int j = 0; j < 8; j++) {
                    const int e = e0 + j * 4;
                    float4 f = zreg[j];
                    uint32_t h01 = pack_bf2(f.x, f.y);
                    uint32_t h23 = pack_bf2(f.z, f.w);
                    uint32_t l01 = pack_bf2(f.x - bf_lo(h01), f.y - bf_hi(h01));
                    uint32_t l23 = pack_bf2(f.z - bf_lo(h23), f.w - bf_hi(h23));
                    int sw = (((e >> 3) ^ xr) << 4) + (e & 4) * 2;
                    *(uint2*)(AH + sw) = make_uint2(h01, h23);
                    *(uint2*)(AL + sw) = make_uint2(l01, l23);
                }
            }
            if (t + 2 < NTILES) {
                const float4* zp = (const float4*)(zrow + (size_t)(t + 2) * TM * E_);
                #pragma unroll
                for (int j = 0; j < 8; j++) zreg[j] = zp[j];
            }
        }
        __syncthreads();
    }

    // ---- softmax + output: 2 warps per head (wid&7 = head, wid>>3 = m-half)
    {
        const int h    = wid & 7;
        const int half = wid >> 3;
        float* srow = s_sm + h * N_;

        float mx = -1e30f;
        for (int m = lane; m < N_; m += 32) mx = fmaxf(mx, srow[m]);
        #pragma unroll
        for (int o = 16; o > 0; o >>= 1) mx = fmaxf(mx, __shfl_xor_sync(0xffffffffu, mx, o));

        float psum = 0.f;
        const int mbeg = half * (N_ / 2);
        for (int m = mbeg + lane; m < mbeg + N_ / 2; m += 32) {
            float e = __expf(srow[m] - mx);
            srow[m] = e;
            psum += e;
        }
        #pragma unroll
        for (int o = 16; o > 0; o >>= 1) psum += __shfl_xor_sync(0xffffffffu, psum, o);
        if (lane == 0) red_sm[h * 2 + half] = psum;
        __syncthreads();
        const float sum = red_sm[h * 2] + red_sm[h * 2 + 1];

        const int d   = lane & 15;
        const int sub = lane >> 4;
        const float* vp = v + (((size_t)b * H_ + h) * N_) * D_;
        float oacc = 0.f;
        const int m0 = mbeg + sub * (N_ / 4);
        #pragma unroll 4
        for (int m = m0; m < m0 + N_ / 4; m++)
            oacc += srow[m] * vp[(size_t)m * D_ + d];
        oacc += __shfl_xor_sync(0xffffffffu, oacc, 16);
        if (half == 1 && sub == 0) obuf[h * 16 + d] = oacc;
        __syncthreads();
        if (half == 0 && sub == 0)
            out[((size_t)b * N_ + n) * HD + h * 16 + d] = (oacc + obuf[h * 16 + d]) / sum;
    }
}

extern "C" void kernel_launch(void* const* d_in, const int* in_sizes, int n_in,
                              void* d_out, int out_size) {
    const float* q   = (const float*)d_in[0];
    const float* k   = (const float*)d_in[1];
    const float* v   = (const float*)d_in[2];
    const float* z   = (const float*)d_in[3];
    const float* Wz1 = (const float*)d_in[4];
    const float* Wz2 = (const float*)d_in[5];
    float* out = (float*)d_out;

    cudaFuncSetAttribute(mixed_attn_ws,
                         cudaFuncAttributeMaxDynamicSharedMemorySize, SM_TOTAL);
    dim3 grid(N_, B_);
    mixed_attn_ws<<<grid, THREADS, SM_TOTAL>>>(q, k, v, z, Wz1, Wz2, out);
}